// round 1
// baseline (speedup 1.0000x reference)
#include <cuda_runtime.h>
#include <cstdint>

#define HGRID 768
#define WGRID 768

// Scratch in __device__ globals (no allocation allowed).
__device__ int   g_idx_map[HGRID * WGRID];
__device__ float g_h1[200064 * 64];   // conv1 output, padded to tile multiple
__device__ float g_h2[200064 * 64];   // conv2 output

// ---------------------------------------------------------------------------
// coords may arrive as int32 or int64 (JAX x64 flag dependent). coords are
// sorted unique >= 0, so coords[1] >= 1. Reinterpreting as int32:
//   int64 layout -> word[1] = high half of coords[0] = 0
//   int32 layout -> word[1] = coords[1] >= 1
__device__ __forceinline__ int coords_is64(const int* c) { return c[1] == 0; }
__device__ __forceinline__ int load_coord(const int* c, int is64, int i) {
    return is64 ? c[2 * i] : c[i];
}

// ---------------------------------------------------------------------------
__global__ void clear_map_kernel() {
    int i = blockIdx.x * blockDim.x + threadIdx.x;
    if (i < HGRID * WGRID) g_idx_map[i] = -1;
}

__global__ void scatter_map_kernel(const int* __restrict__ coords, int n) {
    int i = blockIdx.x * blockDim.x + threadIdx.x;
    int is64 = coords_is64(coords);
    if (i < n) g_idx_map[load_coord(coords, is64, i)] = i;
}

// ---------------------------------------------------------------------------
// Shared micro-kernel: C[128 sites x 64 cols] += A[128 x 32k] * B[32k x 64]
// 256 threads; each thread owns an 8(site) x 4(col) register tile.
// sA row stride = LDA floats (33 or 65: odd -> conflict-free column reads),
// sB row stride = 64 floats (float4 row reads, conflict-free).
template <int LDA>
__device__ __forceinline__ void mm32(const float* __restrict__ sA,
                                     const float* __restrict__ sB,
                                     int trow, int tcol, float acc[8][4]) {
#pragma unroll
    for (int k = 0; k < 32; ++k) {
        float4 b = *(const float4*)(sB + k * 64 + tcol);
#pragma unroll
        for (int i = 0; i < 8; ++i) {
            float a = sA[(trow + i) * LDA + k];
            acc[i][0] = fmaf(a, b.x, acc[i][0]);
            acc[i][1] = fmaf(a, b.y, acc[i][1]);
            acc[i][2] = fmaf(a, b.z, acc[i][2]);
            acc[i][3] = fmaf(a, b.w, acc[i][3]);
        }
    }
}

// ---------------------------------------------------------------------------
// conv1: h1 = relu((feats @ w1) * s1 + b1)   [N,256]x[256,64] -> [N,64]
__global__ void __launch_bounds__(256) conv1_kernel(
    const float* __restrict__ feats, const float* __restrict__ w1,
    const float* __restrict__ s1, const float* __restrict__ b1, int n)
{
    __shared__ __align__(16) float sA[128 * 33];
    __shared__ __align__(16) float sB[32 * 64];
    const int tid = threadIdx.x;
    const int site0 = blockIdx.x * 128;
    const int trow = (tid >> 4) << 3;
    const int tcol = (tid & 15) << 2;

    float acc[8][4];
#pragma unroll
    for (int i = 0; i < 8; ++i)
#pragma unroll
        for (int j = 0; j < 4; ++j) acc[i][j] = 0.f;

#pragma unroll 1
    for (int k0 = 0; k0 < 256; k0 += 32) {
        // feats tile: 128 sites x 32 k
#pragma unroll
        for (int l = 0; l < 4; ++l) {
            int i = tid + l * 256;          // 0..1023
            int r = i >> 3, c4 = (i & 7) << 2;
            int site = site0 + r;
            float4 v = make_float4(0.f, 0.f, 0.f, 0.f);
            if (site < n) v = *(const float4*)&feats[(size_t)site * 256 + k0 + c4];
            sA[r * 33 + c4 + 0] = v.x; sA[r * 33 + c4 + 1] = v.y;
            sA[r * 33 + c4 + 2] = v.z; sA[r * 33 + c4 + 3] = v.w;
        }
        // w1 chunk: 32 k x 64 cols
#pragma unroll
        for (int l = 0; l < 2; ++l) {
            int i = tid + l * 256;          // 0..511 float4 slots
            int r = i >> 4, c4 = (i & 15) << 2;
            *(float4*)&sB[r * 64 + c4] = *(const float4*)&w1[(size_t)(k0 + r) * 64 + c4];
        }
        __syncthreads();
        mm32<33>(sA, sB, trow, tcol, acc);
        __syncthreads();
    }

    float sc[4], bi[4];
#pragma unroll
    for (int j = 0; j < 4; ++j) { sc[j] = s1[tcol + j]; bi[j] = b1[tcol + j]; }
#pragma unroll
    for (int i = 0; i < 8; ++i) {
        int site = site0 + trow + i;
        if (site < n) {
            float4 o;
            o.x = fmaxf(fmaf(acc[i][0], sc[0], bi[0]), 0.f);
            o.y = fmaxf(fmaf(acc[i][1], sc[1], bi[1]), 0.f);
            o.z = fmaxf(fmaf(acc[i][2], sc[2], bi[2]), 0.f);
            o.w = fmaxf(fmaf(acc[i][3], sc[3], bi[3]), 0.f);
            *(float4*)&g_h1[(size_t)site * 64 + tcol] = o;
        }
    }
}

// ---------------------------------------------------------------------------
// conv2: h2 = relu(sparse3x3(h1, w2) * s2 + b2)   9 taps of [N,64]x[64,64]
__global__ void __launch_bounds__(256) conv2_kernel(
    const int* __restrict__ coords, const float* __restrict__ w2,
    const float* __restrict__ s2, const float* __restrict__ b2, int n)
{
    __shared__ __align__(16) float sA[128 * 65];   // gathered h1 rows (full 64 k)
    __shared__ __align__(16) float sB[32 * 64];    // half of w2[tap]
    __shared__ int s_nbr[9][128];

    const int tid = threadIdx.x;
    const int site0 = blockIdx.x * 128;
    const int trow = (tid >> 4) << 3;
    const int tcol = (tid & 15) << 2;

    // Precompute neighbor row indices for all 9 taps.
    if (tid < 128) {
#pragma unroll
        for (int t = 0; t < 9; ++t) s_nbr[t][tid] = -1;
        int site = site0 + tid;
        if (site < n) {
            int is64 = coords_is64(coords);
            int c = load_coord(coords, is64, site);
            int y = c / WGRID, x = c % WGRID;
#pragma unroll
            for (int t = 0; t < 9; ++t) {
                int ny = y + t / 3 - 1, nx = x + t % 3 - 1;
                if (ny >= 0 && ny < HGRID && nx >= 0 && nx < WGRID)
                    s_nbr[t][tid] = g_idx_map[ny * WGRID + nx];
            }
        }
    }
    __syncthreads();

    float acc[8][4];
#pragma unroll
    for (int i = 0; i < 8; ++i)
#pragma unroll
        for (int j = 0; j < 4; ++j) acc[i][j] = 0.f;

#pragma unroll 1
    for (int t = 0; t < 9; ++t) {
        // Gather 128 neighbor rows of h1 (64 floats each); zeros where absent.
#pragma unroll
        for (int l = 0; l < 8; ++l) {
            int i = tid + l * 256;          // 0..2047 float4 slots
            int r = i >> 4, c4 = (i & 15) << 2;
            int nb = s_nbr[t][r];
            float4 v = make_float4(0.f, 0.f, 0.f, 0.f);
            if (nb >= 0) v = *(const float4*)&g_h1[(size_t)nb * 64 + c4];
            sA[r * 65 + c4 + 0] = v.x; sA[r * 65 + c4 + 1] = v.y;
            sA[r * 65 + c4 + 2] = v.z; sA[r * 65 + c4 + 3] = v.w;
        }
        const float* w2t = w2 + (size_t)t * 64 * 64;
        // k chunk 0
#pragma unroll
        for (int l = 0; l < 2; ++l) {
            int i = tid + l * 256;
            int r = i >> 4, c4 = (i & 15) << 2;
            *(float4*)&sB[r * 64 + c4] = *(const float4*)&w2t[r * 64 + c4];
        }
        __syncthreads();
        mm32<65>(sA + 0, sB, trow, tcol, acc);
        __syncthreads();
        // k chunk 1
#pragma unroll
        for (int l = 0; l < 2; ++l) {
            int i = tid + l * 256;
            int r = i >> 4, c4 = (i & 15) << 2;
            *(float4*)&sB[r * 64 + c4] = *(const float4*)&w2t[(32 + r) * 64 + c4];
        }
        __syncthreads();
        mm32<65>(sA + 32, sB, trow, tcol, acc);
        __syncthreads();
    }

    float sc[4], bi[4];
#pragma unroll
    for (int j = 0; j < 4; ++j) { sc[j] = s2[tcol + j]; bi[j] = b2[tcol + j]; }
#pragma unroll
    for (int i = 0; i < 8; ++i) {
        int site = site0 + trow + i;
        if (site < n) {
            float4 o;
            o.x = fmaxf(fmaf(acc[i][0], sc[0], bi[0]), 0.f);
            o.y = fmaxf(fmaf(acc[i][1], sc[1], bi[1]), 0.f);
            o.z = fmaxf(fmaf(acc[i][2], sc[2], bi[2]), 0.f);
            o.w = fmaxf(fmaf(acc[i][3], sc[3], bi[3]), 0.f);
            *(float4*)&g_h2[(size_t)site * 64 + tcol] = o;
        }
    }
}

// ---------------------------------------------------------------------------
// conv3 + residual: out = relu((h2 @ w3) * s3 + b3 + feats)  [N,64]x[64,256]
__global__ void __launch_bounds__(256) conv3_kernel(
    const float* __restrict__ feats, const float* __restrict__ w3,
    const float* __restrict__ s3, const float* __restrict__ b3,
    float* __restrict__ out, int n)
{
    __shared__ __align__(16) float sA[128 * 33];
    __shared__ __align__(16) float sB[32 * 64];
    const int tid = threadIdx.x;
    const int site0 = blockIdx.x * 128;
    const int cb = blockIdx.y * 64;
    const int trow = (tid >> 4) << 3;
    const int tcol = (tid & 15) << 2;

    float acc[8][4];
#pragma unroll
    for (int i = 0; i < 8; ++i)
#pragma unroll
        for (int j = 0; j < 4; ++j) acc[i][j] = 0.f;

#pragma unroll 1
    for (int k0 = 0; k0 < 64; k0 += 32) {
#pragma unroll
        for (int l = 0; l < 4; ++l) {
            int i = tid + l * 256;
            int r = i >> 3, c4 = (i & 7) << 2;
            int site = site0 + r;
            float4 v = make_float4(0.f, 0.f, 0.f, 0.f);
            if (site < n) v = *(const float4*)&g_h2[(size_t)site * 64 + k0 + c4];
            sA[r * 33 + c4 + 0] = v.x; sA[r * 33 + c4 + 1] = v.y;
            sA[r * 33 + c4 + 2] = v.z; sA[r * 33 + c4 + 3] = v.w;
        }
#pragma unroll
        for (int l = 0; l < 2; ++l) {
            int i = tid + l * 256;
            int r = i >> 4, c4 = (i & 15) << 2;
            *(float4*)&sB[r * 64 + c4] =
                *(const float4*)&w3[(size_t)(k0 + r) * 256 + cb + c4];
        }
        __syncthreads();
        mm32<33>(sA, sB, trow, tcol, acc);
        __syncthreads();
    }

    const int col = cb + tcol;
    float sc[4], bi[4];
#pragma unroll
    for (int j = 0; j < 4; ++j) { sc[j] = s3[col + j]; bi[j] = b3[col + j]; }
#pragma unroll
    for (int i = 0; i < 8; ++i) {
        int site = site0 + trow + i;
        if (site < n) {
            float4 idn = *(const float4*)&feats[(size_t)site * 256 + col];
            float4 o;
            o.x = fmaxf(fmaf(acc[i][0], sc[0], bi[0]) + idn.x, 0.f);
            o.y = fmaxf(fmaf(acc[i][1], sc[1], bi[1]) + idn.y, 0.f);
            o.z = fmaxf(fmaf(acc[i][2], sc[2], bi[2]) + idn.z, 0.f);
            o.w = fmaxf(fmaf(acc[i][3], sc[3], bi[3]) + idn.w, 0.f);
            *(float4*)&out[(size_t)site * 256 + col] = o;
        }
    }
}

// ---------------------------------------------------------------------------
extern "C" void kernel_launch(void* const* d_in, const int* in_sizes, int n_in,
                              void* d_out, int out_size) {
    const float* feats  = (const float*)d_in[0];
    const int*   coords = (const int*)d_in[1];    // int32 or int64, detected on-device
    const float* w1     = (const float*)d_in[2];
    const float* w2     = (const float*)d_in[3];
    const float* w3     = (const float*)d_in[4];
    const float* s1     = (const float*)d_in[5];
    const float* b1     = (const float*)d_in[6];
    const float* s2     = (const float*)d_in[7];
    const float* b2     = (const float*)d_in[8];
    const float* s3     = (const float*)d_in[9];
    const float* b3     = (const float*)d_in[10];
    float* out = (float*)d_out;

    const int n = in_sizes[0] / 256;          // active sites
    const int tiles = (n + 127) / 128;

    clear_map_kernel<<<(HGRID * WGRID + 255) / 256, 256>>>();
    scatter_map_kernel<<<(n + 255) / 256, 256>>>(coords, n);
    conv1_kernel<<<tiles, 256>>>(feats, w1, s1, b1, n);
    conv2_kernel<<<tiles, 256>>>(coords, w2, s2, b2, n);
    conv3_kernel<<<dim3(tiles, 4), 256>>>(feats, w3, s3, b3, out, n);
}

// round 3
// speedup vs baseline: 1.2678x; 1.2678x over previous
#include <cuda_runtime.h>
#include <cuda_bf16.h>
#include <cstdint>

#define HGRID 768
#define WGRID 768

// Scratch in __device__ globals (no allocation allowed).
__device__ int   g_idx_map[HGRID * WGRID];
__device__ float g_h1[200064 * 64];   // conv1 output
__device__ float g_h2[200064 * 64];   // conv2 output
// w2 in mma.sync B-fragment layout: [tap][kc(4)][nt(8)][lane(32)] x uint4
//   uint4 = { b_hi_reg0, b_hi_reg1, b_lo_reg0, b_lo_reg1 }
__device__ uint4 g_w2f[9 * 4 * 8 * 32];

// ---------------------------------------------------------------------------
__device__ __forceinline__ int coords_is64(const int* c) { return c[1] == 0; }
__device__ __forceinline__ int load_coord(const int* c, int is64, int i) {
    return is64 ? c[2 * i] : c[i];
}
__device__ __forceinline__ void bsplit2(float a, float b, uint32_t& hi, uint32_t& lo) {
    __nv_bfloat16 ah = __float2bfloat16(a);
    __nv_bfloat16 bh = __float2bfloat16(b);
    float ar = a - __bfloat162float(ah);
    float br = b - __bfloat162float(bh);
    __nv_bfloat162 h; h.x = ah; h.y = bh;
    __nv_bfloat162 l; l.x = __float2bfloat16(ar); l.y = __float2bfloat16(br);
    hi = *reinterpret_cast<uint32_t*>(&h);
    lo = *reinterpret_cast<uint32_t*>(&l);
}
__device__ __forceinline__ uint32_t pack_bf16(float a, float b) {
    __nv_bfloat162 h; h.x = __float2bfloat16(a); h.y = __float2bfloat16(b);
    return *reinterpret_cast<uint32_t*>(&h);
}

// mma.sync m16n8k16 bf16 -> f32 accumulate
__device__ __forceinline__ void mma16816(float c[4], const uint32_t a[4],
                                         uint32_t b0, uint32_t b1) {
    asm volatile(
        "mma.sync.aligned.m16n8k16.row.col.f32.bf16.bf16.f32 "
        "{%0,%1,%2,%3}, {%4,%5,%6,%7}, {%8,%9}, {%0,%1,%2,%3};"
        : "+f"(c[0]), "+f"(c[1]), "+f"(c[2]), "+f"(c[3])
        : "r"(a[0]), "r"(a[1]), "r"(a[2]), "r"(a[3]), "r"(b0), "r"(b1));
}

// ---------------------------------------------------------------------------
__global__ void clear_map_kernel() {
    int i = blockIdx.x * blockDim.x + threadIdx.x;
    if (i < HGRID * WGRID) g_idx_map[i] = -1;
}
__global__ void scatter_map_kernel(const int* __restrict__ coords, int n) {
    int i = blockIdx.x * blockDim.x + threadIdx.x;
    int is64 = coords_is64(coords);
    if (i < n) g_idx_map[load_coord(coords, is64, i)] = i;
}

// w2 [9][64 k][64 n] f32 -> per-lane B fragments (hi/lo bf16 split).
// Fragment mapping for m16n8k16 "col" B: lane holds
//   reg0 = { B[k0][n], B[k0+1][n] },  reg1 = { B[k0+8][n], B[k0+9][n] }
//   with n = nt*8 + lane/4, k0 = kc*16 + (lane%4)*2.
__global__ void prep_w2f_kernel(const float* __restrict__ w2) {
    int i = blockIdx.x * blockDim.x + threadIdx.x;
    if (i >= 9 * 4 * 8 * 32) return;
    int lane = i & 31, nt = (i >> 5) & 7, kc = (i >> 8) & 3, tap = i >> 10;
    int n  = nt * 8 + (lane >> 2);
    int k0 = kc * 16 + (lane & 3) * 2;
    uint32_t hi[2], lo[2];
#pragma unroll
    for (int j = 0; j < 2; ++j) {
        int k = k0 + j * 8;
        float v0 = w2[tap * 4096 + k * 64 + n];
        float v1 = w2[tap * 4096 + (k + 1) * 64 + n];
        bsplit2(v0, v1, hi[j], lo[j]);
    }
    g_w2f[i] = make_uint4(hi[0], hi[1], lo[0], lo[1]);
}

// ---------------------------------------------------------------------------
// FFMA micro-kernel (conv1 / conv3)
template <int LDA>
__device__ __forceinline__ void mm32(const float* __restrict__ sA,
                                     const float* __restrict__ sB,
                                     int trow, int tcol, float acc[8][4]) {
#pragma unroll
    for (int k = 0; k < 32; ++k) {
        float4 b = *(const float4*)(sB + k * 64 + tcol);
#pragma unroll
        for (int i = 0; i < 8; ++i) {
            float a = sA[(trow + i) * LDA + k];
            acc[i][0] = fmaf(a, b.x, acc[i][0]);
            acc[i][1] = fmaf(a, b.y, acc[i][1]);
            acc[i][2] = fmaf(a, b.z, acc[i][2]);
            acc[i][3] = fmaf(a, b.w, acc[i][3]);
        }
    }
}

// conv1: h1 = relu((feats @ w1) * s1 + b1)
__global__ void __launch_bounds__(256) conv1_kernel(
    const float* __restrict__ feats, const float* __restrict__ w1,
    const float* __restrict__ s1, const float* __restrict__ b1, int n)
{
    __shared__ __align__(16) float sA[128 * 33];
    __shared__ __align__(16) float sB[32 * 64];
    const int tid = threadIdx.x;
    const int site0 = blockIdx.x * 128;
    const int trow = (tid >> 4) << 3;
    const int tcol = (tid & 15) << 2;

    float acc[8][4];
#pragma unroll
    for (int i = 0; i < 8; ++i)
#pragma unroll
        for (int j = 0; j < 4; ++j) acc[i][j] = 0.f;

#pragma unroll 1
    for (int k0 = 0; k0 < 256; k0 += 32) {
#pragma unroll
        for (int l = 0; l < 4; ++l) {
            int i = tid + l * 256;
            int r = i >> 3, c4 = (i & 7) << 2;
            int site = site0 + r;
            float4 v = make_float4(0.f, 0.f, 0.f, 0.f);
            if (site < n) v = *(const float4*)&feats[(size_t)site * 256 + k0 + c4];
            sA[r * 33 + c4 + 0] = v.x; sA[r * 33 + c4 + 1] = v.y;
            sA[r * 33 + c4 + 2] = v.z; sA[r * 33 + c4 + 3] = v.w;
        }
#pragma unroll
        for (int l = 0; l < 2; ++l) {
            int i = tid + l * 256;
            int r = i >> 4, c4 = (i & 15) << 2;
            *(float4*)&sB[r * 64 + c4] = *(const float4*)&w1[(size_t)(k0 + r) * 64 + c4];
        }
        __syncthreads();
        mm32<33>(sA, sB, trow, tcol, acc);
        __syncthreads();
    }

    float sc[4], bi[4];
#pragma unroll
    for (int j = 0; j < 4; ++j) { sc[j] = s1[tcol + j]; bi[j] = b1[tcol + j]; }
#pragma unroll
    for (int i = 0; i < 8; ++i) {
        int site = site0 + trow + i;
        if (site < n) {
            float4 o;
            o.x = fmaxf(fmaf(acc[i][0], sc[0], bi[0]), 0.f);
            o.y = fmaxf(fmaf(acc[i][1], sc[1], bi[1]), 0.f);
            o.z = fmaxf(fmaf(acc[i][2], sc[2], bi[2]), 0.f);
            o.w = fmaxf(fmaf(acc[i][3], sc[3], bi[3]), 0.f);
            *(float4*)&g_h1[(size_t)site * 64 + tcol] = o;
        }
    }
}

// ---------------------------------------------------------------------------
// conv2 via mma.sync bf16 (3-term split). 256 threads = 8 warps; each warp
// owns 16 sites x 64 cols; accumulators persist across all 9 taps.
#define LDA2 144   // A row stride in bytes (72 bf16) -> conflict-free frags

__global__ void __launch_bounds__(256) conv2_mma_kernel(
    const int* __restrict__ coords,
    const float* __restrict__ s2, const float* __restrict__ b2, int n)
{
    __shared__ int s_nbr[9 * 128];
    __shared__ float s_s2[64], s_b2[64];
    __shared__ __align__(16) unsigned char sA[2][128 * LDA2];  // hi, lo planes

    const int tid = threadIdx.x, wid = tid >> 5, lane = tid & 31;
    const int site0 = blockIdx.x * 128;

    if (tid < 64) { s_s2[tid] = s2[tid]; s_b2[tid] = b2[tid]; }
    if (tid < 128) {
#pragma unroll
        for (int t = 0; t < 9; ++t) s_nbr[t * 128 + tid] = -1;
        int site = site0 + tid;
        if (site < n) {
            int is64 = coords_is64(coords);
            int c = load_coord(coords, is64, site);
            int y = c / WGRID, x = c % WGRID;
#pragma unroll
            for (int t = 0; t < 9; ++t) {
                int ny = y + t / 3 - 1, nx = x + t % 3 - 1;
                if (ny >= 0 && ny < HGRID && nx >= 0 && nx < WGRID)
                    s_nbr[t * 128 + tid] = g_idx_map[ny * WGRID + nx];
            }
        }
    }
    __syncthreads();

    float acc[8][4];
#pragma unroll
    for (int t = 0; t < 8; ++t)
#pragma unroll
        for (int j = 0; j < 4; ++j) acc[t][j] = 0.f;

    const int rw = wid * 16;                 // warp's row base
    const int r2 = tid >> 1, half = tid & 1; // gather: 2 threads / row

#pragma unroll 1
    for (int tap = 0; tap < 9; ++tap) {
        // --- gather 128 neighbor rows of h1, split into bf16 hi/lo planes ---
        {
            int nb = s_nbr[tap * 128 + r2];
            const float4* src =
                (const float4*)(g_h1 + ((size_t)(nb < 0 ? 0 : nb)) * 64 + half * 32);
            uint32_t off = (uint32_t)(r2 * LDA2 + half * 64);
#pragma unroll
            for (int g = 0; g < 4; ++g) {
                float4 v0 = make_float4(0.f, 0.f, 0.f, 0.f), v1 = v0;
                if (nb >= 0) { v0 = src[2 * g]; v1 = src[2 * g + 1]; }
                uint4 hi4, lo4;
                bsplit2(v0.x, v0.y, hi4.x, lo4.x);
                bsplit2(v0.z, v0.w, hi4.y, lo4.y);
                bsplit2(v1.x, v1.y, hi4.z, lo4.z);
                bsplit2(v1.z, v1.w, hi4.w, lo4.w);
                *(uint4*)(&sA[0][0] + off + g * 16) = hi4;
                *(uint4*)(&sA[1][0] + off + g * 16) = lo4;
            }
        }
        __syncthreads();

        // --- mma: 4 k-chunks x 8 n-tiles x 3 split terms ---
        const uint4* wf = g_w2f + (size_t)tap * 1024 + lane;
#pragma unroll
        for (int kc = 0; kc < 4; ++kc) {
            uint32_t abase = (uint32_t)((rw + (lane >> 2)) * LDA2 +
                                        kc * 32 + (lane & 3) * 4);
            uint32_t ah[4], al[4];
            ah[0] = *(const uint32_t*)(&sA[0][0] + abase);
            ah[1] = *(const uint32_t*)(&sA[0][0] + abase + 8 * LDA2);
            ah[2] = *(const uint32_t*)(&sA[0][0] + abase + 16);
            ah[3] = *(const uint32_t*)(&sA[0][0] + abase + 8 * LDA2 + 16);
            al[0] = *(const uint32_t*)(&sA[1][0] + abase);
            al[1] = *(const uint32_t*)(&sA[1][0] + abase + 8 * LDA2);
            al[2] = *(const uint32_t*)(&sA[1][0] + abase + 16);
            al[3] = *(const uint32_t*)(&sA[1][0] + abase + 8 * LDA2 + 16);
#pragma unroll
            for (int nt = 0; nt < 8; ++nt) {
                uint4 b = wf[kc * 256 + nt * 32];
                mma16816(acc[nt], ah, b.x, b.y);   // Ah * Bh
                mma16816(acc[nt], ah, b.z, b.w);   // Ah * Bl
                mma16816(acc[nt], al, b.x, b.y);   // Al * Bh
            }
        }
        __syncthreads();
    }

    // --- epilogue: bn + relu, stage to smem, coalesced write ---
    float* stg = (float*)&sA[0][0];   // 128 x 64 f32 = 32KB (fits in sA)
    {
        int r0 = rw + (lane >> 2);
        int ncol0 = (lane & 3) * 2;
#pragma unroll
        for (int nt = 0; nt < 8; ++nt) {
            int n0 = nt * 8 + ncol0;
            stg[r0 * 64 + n0]           = fmaxf(fmaf(acc[nt][0], s_s2[n0],     s_b2[n0]),     0.f);
            stg[r0 * 64 + n0 + 1]       = fmaxf(fmaf(acc[nt][1], s_s2[n0 + 1], s_b2[n0 + 1]), 0.f);
            stg[(r0 + 8) * 64 + n0]     = fmaxf(fmaf(acc[nt][2], s_s2[n0],     s_b2[n0]),     0.f);
            stg[(r0 + 8) * 64 + n0 + 1] = fmaxf(fmaf(acc[nt][3], s_s2[n0 + 1], s_b2[n0 + 1]), 0.f);
        }
    }
    __syncthreads();
    {
        int site = site0 + r2;
        if (site < n) {
            float4* dst = (float4*)(g_h2 + (size_t)site * 64 + half * 32);
            const float4* s = (const float4*)(stg + r2 * 64 + half * 32);
#pragma unroll
            for (int j = 0; j < 8; ++j) dst[j] = s[j];
        }
    }
}

// ---------------------------------------------------------------------------
// conv3 + residual: out = relu((h2 @ w3) * s3 + b3 + feats)
__global__ void __launch_bounds__(256) conv3_kernel(
    const float* __restrict__ feats, const float* __restrict__ w3,
    const float* __restrict__ s3, const float* __restrict__ b3,
    float* __restrict__ out, int n)
{
    __shared__ __align__(16) float sA[128 * 33];
    __shared__ __align__(16) float sB[32 * 64];
    const int tid = threadIdx.x;
    const int site0 = blockIdx.x * 128;
    const int cb = blockIdx.y * 64;
    const int trow = (tid >> 4) << 3;
    const int tcol = (tid & 15) << 2;

    float acc[8][4];
#pragma unroll
    for (int i = 0; i < 8; ++i)
#pragma unroll
        for (int j = 0; j < 4; ++j) acc[i][j] = 0.f;

#pragma unroll 1
    for (int k0 = 0; k0 < 64; k0 += 32) {
#pragma unroll
        for (int l = 0; l < 4; ++l) {
            int i = tid + l * 256;
            int r = i >> 3, c4 = (i & 7) << 2;
            int site = site0 + r;
            float4 v = make_float4(0.f, 0.f, 0.f, 0.f);
            if (site < n) v = *(const float4*)&g_h2[(size_t)site * 64 + k0 + c4];
            sA[r * 33 + c4 + 0] = v.x; sA[r * 33 + c4 + 1] = v.y;
            sA[r * 33 + c4 + 2] = v.z; sA[r * 33 + c4 + 3] = v.w;
        }
#pragma unroll
        for (int l = 0; l < 2; ++l) {
            int i = tid + l * 256;
            int r = i >> 4, c4 = (i & 15) << 2;
            *(float4*)&sB[r * 64 + c4] =
                *(const float4*)&w3[(size_t)(k0 + r) * 256 + cb + c4];
        }
        __syncthreads();
        mm32<33>(sA, sB, trow, tcol, acc);
        __syncthreads();
    }

    const int col = cb + tcol;
    float sc[4], bi[4];
#pragma unroll
    for (int j = 0; j < 4; ++j) { sc[j] = s3[col + j]; bi[j] = b3[col + j]; }
#pragma unroll
    for (int i = 0; i < 8; ++i) {
        int site = site0 + trow + i;
        if (site < n) {
            float4 idn = *(const float4*)&feats[(size_t)site * 256 + col];
            float4 o;
            o.x = fmaxf(fmaf(acc[i][0], sc[0], bi[0]) + idn.x, 0.f);
            o.y = fmaxf(fmaf(acc[i][1], sc[1], bi[1]) + idn.y, 0.f);
            o.z = fmaxf(fmaf(acc[i][2], sc[2], bi[2]) + idn.z, 0.f);
            o.w = fmaxf(fmaf(acc[i][3], sc[3], bi[3]) + idn.w, 0.f);
            *(float4*)&out[(size_t)site * 256 + col] = o;
        }
    }
}

// ---------------------------------------------------------------------------
extern "C" void kernel_launch(void* const* d_in, const int* in_sizes, int n_in,
                              void* d_out, int out_size) {
    const float* feats  = (const float*)d_in[0];
    const int*   coords = (const int*)d_in[1];
    const float* w1     = (const float*)d_in[2];
    const float* w2     = (const float*)d_in[3];
    const float* w3     = (const float*)d_in[4];
    const float* s1     = (const float*)d_in[5];
    const float* b1     = (const float*)d_in[6];
    const float* s2     = (const float*)d_in[7];
    const float* b2     = (const float*)d_in[8];
    const float* s3     = (const float*)d_in[9];
    const float* b3     = (const float*)d_in[10];
    float* out = (float*)d_out;

    const int n = in_sizes[0] / 256;
    const int tiles = (n + 127) / 128;

    clear_map_kernel<<<(HGRID * WGRID + 255) / 256, 256>>>();
    scatter_map_kernel<<<(n + 255) / 256, 256>>>(coords, n);
    prep_w2f_kernel<<<(9 * 4 * 8 * 32 + 255) / 256, 256>>>(w2);
    conv1_kernel<<<tiles, 256>>>(feats, w1, s1, b1, n);
    conv2_mma_kernel<<<tiles, 256>>>(coords, s2, b2, n);
    conv3_kernel<<<dim3(tiles, 4), 256>>>(feats, w3, s3, b3, out, n);
}